// round 16
// baseline (speedup 1.0000x reference)
#include <cuda_runtime.h>

#define NW 12
#define NL 3
#define DIM 4096
#define BATCH 512
#define NT 512
#define GRID 296
#define FULL2 216
#define PADDED (DIM + DIM / 8)           // 4608 elements
#define DYN_SMEM (PADDED * 16)           // 73,728 B of ulonglong2 {re,im}

typedef unsigned long long ull;

__device__ __forceinline__ ull pk(float lo, float hi) {
    ull r; asm("mov.b64 %0,{%1,%2};" : "=l"(r) : "f"(lo), "f"(hi)); return r;
}
__device__ __forceinline__ void unpk(ull v, float& a, float& b) {
    asm("mov.b64 {%0,%1},%2;" : "=f"(a), "=f"(b) : "l"(v));
}
__device__ __forceinline__ ull mul2(ull a, ull b) {
    ull r; asm("mul.rn.f32x2 %0,%1,%2;" : "=l"(r) : "l"(a), "l"(b)); return r;
}
__device__ __forceinline__ ull fma2(ull a, ull b, ull c) {
    ull r; asm("fma.rn.f32x2 %0,%1,%2,%3;" : "=l"(r) : "l"(a), "l"(b), "l"(c)); return r;
}
__device__ __forceinline__ float2 cmulf(float2 a, float2 b) {
    return make_float2(a.x * b.x - a.y * b.y, a.x * b.y + a.y * b.x);
}
__device__ __forceinline__ void nbar(int id, int cnt) {
    asm volatile("bar.sync %0, %1;" :: "r"(id), "r"(cnt) : "memory");
}

// pad every 8 -> conflict-free 128-bit remap phases
__device__ __forceinline__ int pidx(int i) { return i + (i >> 3); }

// 8 packed amps (2 batch rows per lane). Real RY gates. bit j <-> wire (wbase-j).
__device__ __forceinline__ void apply_group3(ull rp[8], ull ip[8],
                                             const float2* __restrict__ Ucs,
                                             int bg, int wbase)
{
#pragma unroll
    for (int j = 0; j < 3; j++) {
        float2 cs = Ucs[bg + (wbase - j)];
        ull C = pk(cs.x, cs.x), S = pk(cs.y, cs.y), Sn = pk(-cs.y, -cs.y);
#pragma unroll
        for (int p = 0; p < 4; p++) {
            int k0 = ((p >> j) << (j + 1)) | (p & ((1 << j) - 1));
            int k1 = k0 | (1 << j);
            ull R0 = rp[k0], Q0 = ip[k0], R1 = rp[k1], Q1 = ip[k1];
            rp[k0] = fma2(Sn, R1, mul2(C, R0));
            ip[k0] = fma2(Sn, Q1, mul2(C, Q0));
            rp[k1] = fma2(S, R0, mul2(C, R1));
            ip[k1] = fma2(S, Q0, mul2(C, Q1));
        }
    }
}

__global__ __launch_bounds__(NT, 2)
void qsim_kernel(const float* __restrict__ state,
                 const float* __restrict__ weights,
                 const float* __restrict__ head_w,
                 const float* __restrict__ head_b,
                 float* __restrict__ out)
{
    extern __shared__ ulonglong2 buf[];    // [PADDED] {re_pack, im_pack}
    __shared__ float2 Ucs[NL * NW];        // (cos th/2, sin th/2)
    __shared__ float alpha1[NL * NW];      // D1 |1>-phase
    __shared__ float dgam[NL * NW];        // D2 phase delta
    __shared__ float2 T0lo[64], T0hi[64];          // init e^{i phi1^0}
    __shared__ float2 TLo[NL - 1][128];            // boundary: (i&63) | P<<6
    __shared__ float2 THi[NL - 1][64];             // boundary: i>>6
    __shared__ float hw[NW];
    __shared__ ull warpsum[NT / 32];

    const int tid = threadIdx.x;
    const int b = blockIdx.x;
    const int r0 = b;
    const bool has2 = (b < FULL2);
    const int r1 = has2 ? (b + GRID) : b;   // dummy aliases row r0 (no OOB)

    // ---- issue global loads early ----
    const float4* s0p = (const float4*)(state + (size_t)r0 * DIM);
    const float4* s1p = (const float4*)(state + (size_t)r1 * DIM);
    float4 v0[2], v1[2];
#pragma unroll
    for (int q = 0; q < 2; q++) { v0[q] = s0p[tid * 2 + q]; v1[q] = s1p[tid * 2 + q]; }

    // ---- ZYZ: U = e^{id} D2 RY(th) D1 ----
    if (tid < NL * NW) {
        float a = weights[tid * 3 + 0];
        float bb = weights[tid * 3 + 1];
        float c = weights[tid * 3 + 2];
        float sa, ca, sb, cb, sc, cc;
        sincosf(0.5f * a, &sa, &ca);
        sincosf(0.5f * bb, &sb, &cb);
        sincosf(0.5f * c, &sc, &cc);
        float m00r = cb * ca, m00i = sb * sa;
        float m01r = -sb * ca, m01i = -cb * sa;
        float m10r = sb * ca, m10i = -cb * sa;
        float u00r = m00r * cc + m00i * sc, u00i = m00i * cc - m00r * sc;
        float u01r = m01r * cc + m01i * sc, u01i = m01i * cc - m01r * sc;
        float u10r = m10r * cc - m10i * sc, u10i = m10i * cc + m10r * sc;
        float cth = sqrtf(u00r * u00r + u00i * u00i);
        float sth = sqrtf(u10r * u10r + u10i * u10i);
        float g0 = atan2f(u00i, u00r);
        float g1 = atan2f(u10i, u10r);
        Ucs[tid] = make_float2(cth, sth);
        alpha1[tid] = atan2f(-u01i, -u01r) - g0;
        dgam[tid] = g1 - g0;
    }
    if (tid < NW) hw[tid] = head_w[tid];
    __syncthreads();

    // ---- phase tables ----
    // init phases: phi1^0 split lo (x bits 0-5 -> wires 11-6) / hi (6-11 -> 5-0)
    if (tid < 64) {
        int m = tid;
        float plo = 0.f, phi = 0.f;
#pragma unroll
        for (int j = 0; j < 6; j++) {
            if ((m >> j) & 1) { plo += alpha1[11 - j]; phi += alpha1[5 - j]; }
        }
        float cv, sv;
        sincosf(plo, &sv, &cv); T0lo[m] = make_float2(cv, sv);
        sincosf(phi, &sv, &cv); T0hi[m] = make_float2(cv, sv);
        // boundary hi: m = i>>6 (src). dst bits: y_{6+j} = parity(m>>j).
#pragma unroll
        for (int l = 0; l < NL - 1; l++) {
            float ph = 0.f;
#pragma unroll
            for (int j = 0; j < 6; j++) {
                if ((m >> j) & 1) ph += dgam[l * NW + 5 - j];
                if (__popc(m >> j) & 1) ph += alpha1[(l + 1) * NW + 5 - j];
            }
            sincosf(ph, &sv, &cv); THi[l][m] = make_float2(cv, sv);
        }
    }
    // boundary lo: index = (i&63) | P<<6, P = parity(i>>6).
    // y_j (j<6) = parity(m>>j) ^ P.
    if (tid < 128) {
        int m = tid & 63;
        int P = tid >> 6;
#pragma unroll
        for (int l = 0; l < NL - 1; l++) {
            float ph = 0.f;
#pragma unroll
            for (int j = 0; j < 6; j++) {
                if ((m >> j) & 1) ph += dgam[l * NW + 11 - j];
                if ((__popc(m >> j) & 1) ^ P) ph += alpha1[(l + 1) * NW + 11 - j];
            }
            float cv, sv;
            sincosf(ph, &sv, &cv); TLo[l][tid] = make_float2(cv, sv);
        }
    }
    __syncthreads();

    // ---- init: psi[x] = s(x) e^{i phi1^0(x)}, mapping A: x = (tid<<3)|k ----
    ull rp[8], ip[8];
    {
        float2 hiC = T0hi[tid >> 3];   // x>>6 = tid>>3
        float a0[8], a1[8];
        a0[0] = v0[0].x; a0[1] = v0[0].y; a0[2] = v0[0].z; a0[3] = v0[0].w;
        a0[4] = v0[1].x; a0[5] = v0[1].y; a0[6] = v0[1].z; a0[7] = v0[1].w;
        a1[0] = v1[0].x; a1[1] = v1[0].y; a1[2] = v1[0].z; a1[3] = v1[0].w;
        a1[4] = v1[1].x; a1[5] = v1[1].y; a1[6] = v1[1].z; a1[7] = v1[1].w;
#pragma unroll
        for (int k = 0; k < 8; k++) {
            float2 ph = cmulf(T0lo[((tid & 7) << 3) | k], hiC);
            ull sp = pk(a0[k], a1[k]);
            rp[k] = mul2(sp, pk(ph.x, ph.x));
            ip[k] = mul2(sp, pk(ph.y, ph.y));
        }
    }

    // named-barrier group ids
    const int gBC = 1 + ((tid >> 6) & 7);   // 2-warp groups (tid bits 6-8)
    const int gCD = 9 + ((tid >> 5) & 1);   // 8-warp groups (tid bit 5)

    // thread constants for the boundary scatter-write
    int T9 = tid; T9 ^= T9 >> 1; T9 ^= T9 >> 2; T9 ^= T9 >> 4; T9 ^= T9 >> 8;
    T9 &= 511;                              // suffix-XOR of tid (9 bits)
    const int pt6 = __popc(tid >> 6) & 1;   // parity of tid bits 6-8

    for (int l = 0; l < NL; l++) {
        const int bg = l * NW;

        // group A: bits 0-2 -> wires 11,10,9
        apply_group3(rp, ip, Ucs, bg, 11);

        // remap A -> B (intra-8-thread). No WAR barrier needed: slots
        // tid*9+k were last read by this thread (boundary read / fresh).
        {
            ulonglong2* wp = buf + tid * 9;
#pragma unroll
            for (int k = 0; k < 8; k++)
                wp[k] = make_ulonglong2(rp[k], ip[k]);  // pidx((tid<<3)|k)
        }
        __syncwarp();
#pragma unroll
        for (int k = 0; k < 8; k++) {
            int i = ((tid >> 3) << 6) | (k << 3) | (tid & 7);
            ulonglong2 v = buf[pidx(i)];
            rp[k] = v.x; ip[k] = v.y;
        }

        // group B: bits 3-5 -> wires 8,7,6
        apply_group3(rp, ip, Ucs, bg, 8);

        // remap B -> C. Write slots == A->B read slots (ownership).
#pragma unroll
        for (int k = 0; k < 8; k++) {
            int i = ((tid >> 3) << 6) | (k << 3) | (tid & 7);
            buf[pidx(i)] = make_ulonglong2(rp[k], ip[k]);
        }
        nbar(gBC, 64);
#pragma unroll
        for (int k = 0; k < 8; k++) {
            int i = ((tid >> 6) << 9) | (k << 6) | (tid & 63);
            ulonglong2 v = buf[pidx(i)];
            rp[k] = v.x; ip[k] = v.y;
        }

        // group C: bits 6-8 -> wires 5,4,3
        apply_group3(rp, ip, Ucs, bg, 5);

        // remap C -> D. Write slots == B->C read slots (ownership).
#pragma unroll
        for (int k = 0; k < 8; k++) {
            int i = ((tid >> 6) << 9) | (k << 6) | (tid & 63);
            buf[pidx(i)] = make_ulonglong2(rp[k], ip[k]);
        }
        nbar(gCD, 256);
#pragma unroll
        for (int k = 0; k < 8; k++) {
            int i = (k << 9) | tid;
            ulonglong2 v = buf[pidx(i)];
            rp[k] = v.x; ip[k] = v.y;
        }

        // group D: bits 9-11 -> wires 2,1,0
        apply_group3(rp, ip, Ucs, bg, 2);

        // boundary: CNOT perm + merged diagonal via WRITE-SCATTER.
        // Thread holds psi[i], i=(k<<9)|tid; dst y = sxor(i);
        // stores e^{i[phi1^{l+1}(y)+phi2^l(i)]} psi[i] at slot pidx(y).
        // Write pattern conflict-free; read is linear (= next A-write slots).
        if (l < NL - 1) {
            ull nr[8], ni[8];
            int ys[8];
            float2 lo0 = TLo[l][tid & 63];
            float2 lo1 = TLo[l][(tid & 63) | 64];
#pragma unroll
            for (int k = 0; k < 8; k++) {
                const int sx3 = k ^ (k >> 1) ^ (k >> 2);   // dst high bits
                const int pkk = sx3 & 1;                   // parity(k)
                ys[k] = (sx3 << 9) | (T9 ^ (pkk ? 511 : 0));
                float2 hi = THi[l][(k << 3) | (tid >> 6)];
                float2 ph = cmulf(hi, (pkk ^ pt6) ? lo1 : lo0);
                ull C = pk(ph.x, ph.x), S = pk(ph.y, ph.y), Sn = pk(-ph.y, -ph.y);
                nr[k] = fma2(Sn, ip[k], mul2(C, rp[k]));
                ni[k] = fma2(S, rp[k], mul2(C, ip[k]));
            }
            __syncthreads();   // WAR: scatter-write vs all C->D reads
#pragma unroll
            for (int k = 0; k < 8; k++)
                buf[pidx(ys[k])] = make_ulonglong2(nr[k], ni[k]);
            __syncthreads();   // RAW: linear reads see scattered writes
            {
                const ulonglong2* rpn = buf + tid * 9;
#pragma unroll
                for (int k = 0; k < 8; k++) {
                    ulonglong2 v = rpn[k];   // pidx((tid<<3)|k)
                    rp[k] = v.x; ip[k] = v.y;
                }
            }
        }
    }

    // ---- measurement (mapping D): final D2 dropped; last CNOT perm folded
    // into weights. x = (k<<9)|tid -> weight c(suffixXOR(x))
    int m9 = T9;   // suffix-XOR of tid (9 bits), computed above
    float c_low = 0.f;
#pragma unroll
    for (int w = 3; w < 12; w++) {
        c_low += ((m9 >> (11 - w)) & 1) ? -hw[w] : hw[w];
    }
    ull acc2 = 0ULL;
#pragma unroll
    for (int k = 0; k < 8; k++) {
        int g = k;
        g ^= g >> 1; g ^= g >> 2;  // 3-bit suffix-XOR
        float c_high = 0.f;
#pragma unroll
        for (int w = 0; w < 3; w++) {
            c_high += ((g >> (2 - w)) & 1) ? -hw[w] : hw[w];
        }
        float c = c_high + ((g & 1) ? -c_low : c_low);
        ull pr2 = fma2(rp[k], rp[k], mul2(ip[k], ip[k]));  // |psi|^2 both lanes
        acc2 = fma2(pr2, pk(c, c), acc2);
    }
#pragma unroll
    for (int o = 16; o > 0; o >>= 1) {
        float lo, hi;
        unpk(acc2, lo, hi);
        lo += __shfl_xor_sync(0xffffffffu, lo, o);
        hi += __shfl_xor_sync(0xffffffffu, hi, o);
        acc2 = pk(lo, hi);
    }
    if ((tid & 31) == 0) warpsum[tid >> 5] = acc2;
    __syncthreads();
    if (tid == 0) {
        float slo = 0.f, shi = 0.f;
#pragma unroll
        for (int i = 0; i < NT / 32; i++) {
            float lo, hi;
            unpk(warpsum[i], lo, hi);
            slo += lo; shi += hi;
        }
        float bias = head_b[0];
        out[r0] = slo + bias;
        if (has2) out[r1] = shi + bias;
    }
}

extern "C" void kernel_launch(void* const* d_in, const int* in_sizes, int n_in,
                              void* d_out, int out_size)
{
    const float* state   = (const float*)d_in[0];  // (512, 4096)
    const float* weights = (const float*)d_in[1];  // (3, 12, 3)
    const float* head_w  = (const float*)d_in[2];  // (1, 12)
    const float* head_b  = (const float*)d_in[3];  // (1,)
    float* out = (float*)d_out;                    // (512,)
    cudaFuncSetAttribute(qsim_kernel, cudaFuncAttributeMaxDynamicSharedMemorySize, DYN_SMEM);
    qsim_kernel<<<GRID, NT, DYN_SMEM>>>(state, weights, head_w, head_b, out);
}

// round 17
// speedup vs baseline: 1.0243x; 1.0243x over previous
#include <cuda_runtime.h>

#define NW 12
#define NL 3
#define DIM 4096
#define BATCH 512
#define NT 512
#define GRID 296
#define FULL2 216
#define PADDED (DIM + DIM / 8)           // 4608 elements
#define DYN_SMEM (PADDED * 16)           // 73,728 B of ulonglong2 {re,im}

typedef unsigned long long ull;

__device__ __forceinline__ ull pk(float lo, float hi) {
    ull r; asm("mov.b64 %0,{%1,%2};" : "=l"(r) : "f"(lo), "f"(hi)); return r;
}
__device__ __forceinline__ void unpk(ull v, float& a, float& b) {
    asm("mov.b64 {%0,%1},%2;" : "=f"(a), "=f"(b) : "l"(v));
}
__device__ __forceinline__ ull mul2(ull a, ull b) {
    ull r; asm("mul.rn.f32x2 %0,%1,%2;" : "=l"(r) : "l"(a), "l"(b)); return r;
}
__device__ __forceinline__ ull fma2(ull a, ull b, ull c) {
    ull r; asm("fma.rn.f32x2 %0,%1,%2,%3;" : "=l"(r) : "l"(a), "l"(b), "l"(c)); return r;
}
__device__ __forceinline__ float2 cmulf(float2 a, float2 b) {
    return make_float2(a.x * b.x - a.y * b.y, a.x * b.y + a.y * b.x);
}
__device__ __forceinline__ void nbar(int id, int cnt) {
    asm volatile("bar.sync %0, %1;" :: "r"(id), "r"(cnt) : "memory");
}

// pad every 8 -> conflict-free 128-bit remap phases
__device__ __forceinline__ int pidx(int i) { return i + (i >> 3); }

// 8 packed amps (2 batch rows per lane). Real RY gates. bit j <-> wire (wbase-j).
__device__ __forceinline__ void apply_group3(ull rp[8], ull ip[8],
                                             const float2* __restrict__ Ucs,
                                             int bg, int wbase)
{
#pragma unroll
    for (int j = 0; j < 3; j++) {
        float2 cs = Ucs[bg + (wbase - j)];
        ull C = pk(cs.x, cs.x), S = pk(cs.y, cs.y), Sn = pk(-cs.y, -cs.y);
#pragma unroll
        for (int p = 0; p < 4; p++) {
            int k0 = ((p >> j) << (j + 1)) | (p & ((1 << j) - 1));
            int k1 = k0 | (1 << j);
            ull R0 = rp[k0], Q0 = ip[k0], R1 = rp[k1], Q1 = ip[k1];
            rp[k0] = fma2(Sn, R1, mul2(C, R0));
            ip[k0] = fma2(Sn, Q1, mul2(C, Q0));
            rp[k1] = fma2(S, R0, mul2(C, R1));
            ip[k1] = fma2(S, Q0, mul2(C, Q1));
        }
    }
}

__global__ __launch_bounds__(NT, 2)
void qsim_kernel(const float* __restrict__ state,
                 const float* __restrict__ weights,
                 const float* __restrict__ head_w,
                 const float* __restrict__ head_b,
                 float* __restrict__ out)
{
    extern __shared__ ulonglong2 buf[];    // [PADDED] {re_pack, im_pack}
    __shared__ float2 Ucs[NL * NW];        // (cos th/2, sin th/2)
    __shared__ float alpha1[NL * NW];      // D1 |1>-phase
    __shared__ float dgam[NL * NW];        // D2 phase delta
    __shared__ float2 T0lo[64], T0hi[64];          // init e^{i phi1^0}
    __shared__ float2 TLo[NL - 1][128];            // boundary: (i&63) | P<<6
    __shared__ float2 THi[NL - 1][64];             // boundary: i>>6
    __shared__ float hw[NW];
    __shared__ ull warpsum[NT / 32];

    const int tid = threadIdx.x;
    const int b = blockIdx.x;
    const int r0 = b;
    const bool has2 = (b < FULL2);
    const int r1 = has2 ? (b + GRID) : b;   // dummy aliases row r0 (no OOB)

    // ---- issue global loads early ----
    const float4* s0p = (const float4*)(state + (size_t)r0 * DIM);
    const float4* s1p = (const float4*)(state + (size_t)r1 * DIM);
    float4 v0[2], v1[2];
#pragma unroll
    for (int q = 0; q < 2; q++) { v0[q] = s0p[tid * 2 + q]; v1[q] = s1p[tid * 2 + q]; }

    // ---- ZYZ: U = e^{id} D2 RY(th) D1 ----
    if (tid < NL * NW) {
        float a = weights[tid * 3 + 0];
        float bb = weights[tid * 3 + 1];
        float c = weights[tid * 3 + 2];
        float sa, ca, sb, cb, sc, cc;
        sincosf(0.5f * a, &sa, &ca);
        sincosf(0.5f * bb, &sb, &cb);
        sincosf(0.5f * c, &sc, &cc);
        float m00r = cb * ca, m00i = sb * sa;
        float m01r = -sb * ca, m01i = -cb * sa;
        float m10r = sb * ca, m10i = -cb * sa;
        float u00r = m00r * cc + m00i * sc, u00i = m00i * cc - m00r * sc;
        float u01r = m01r * cc + m01i * sc, u01i = m01i * cc - m01r * sc;
        float u10r = m10r * cc - m10i * sc, u10i = m10i * cc + m10r * sc;
        float cth = sqrtf(u00r * u00r + u00i * u00i);
        float sth = sqrtf(u10r * u10r + u10i * u10i);
        float g0 = atan2f(u00i, u00r);
        float g1 = atan2f(u10i, u10r);
        Ucs[tid] = make_float2(cth, sth);
        alpha1[tid] = atan2f(-u01i, -u01r) - g0;
        dgam[tid] = g1 - g0;
    }
    if (tid < NW) hw[tid] = head_w[tid];
    __syncthreads();

    // ---- phase tables ----
    // init phases: phi1^0 split lo (x bits 0-5 -> wires 11-6) / hi (6-11 -> 5-0)
    if (tid < 64) {
        int m = tid;
        float plo = 0.f, phi = 0.f;
#pragma unroll
        for (int j = 0; j < 6; j++) {
            if ((m >> j) & 1) { plo += alpha1[11 - j]; phi += alpha1[5 - j]; }
        }
        float cv, sv;
        sincosf(plo, &sv, &cv); T0lo[m] = make_float2(cv, sv);
        sincosf(phi, &sv, &cv); T0hi[m] = make_float2(cv, sv);
        // boundary hi: m = i>>6 (src). dst bits: y_{6+j} = parity(m>>j).
#pragma unroll
        for (int l = 0; l < NL - 1; l++) {
            float ph = 0.f;
#pragma unroll
            for (int j = 0; j < 6; j++) {
                if ((m >> j) & 1) ph += dgam[l * NW + 5 - j];
                if (__popc(m >> j) & 1) ph += alpha1[(l + 1) * NW + 5 - j];
            }
            sincosf(ph, &sv, &cv); THi[l][m] = make_float2(cv, sv);
        }
    }
    // boundary lo: index = (i&63) | P<<6, P = parity(i>>6).
    // y_j (j<6) = parity(m>>j) ^ P.
    if (tid < 128) {
        int m = tid & 63;
        int P = tid >> 6;
#pragma unroll
        for (int l = 0; l < NL - 1; l++) {
            float ph = 0.f;
#pragma unroll
            for (int j = 0; j < 6; j++) {
                if ((m >> j) & 1) ph += dgam[l * NW + 11 - j];
                if ((__popc(m >> j) & 1) ^ P) ph += alpha1[(l + 1) * NW + 11 - j];
            }
            float cv, sv;
            sincosf(ph, &sv, &cv); TLo[l][tid] = make_float2(cv, sv);
        }
    }
    __syncthreads();

    // ---- init: psi[x] = s(x) e^{i phi1^0(x)}, mapping A: x = (tid<<3)|k ----
    ull rp[8], ip[8];
    {
        float2 hiC = T0hi[tid >> 3];   // x>>6 = tid>>3
        float a0[8], a1[8];
        a0[0] = v0[0].x; a0[1] = v0[0].y; a0[2] = v0[0].z; a0[3] = v0[0].w;
        a0[4] = v0[1].x; a0[5] = v0[1].y; a0[6] = v0[1].z; a0[7] = v0[1].w;
        a1[0] = v1[0].x; a1[1] = v1[0].y; a1[2] = v1[0].z; a1[3] = v1[0].w;
        a1[4] = v1[1].x; a1[5] = v1[1].y; a1[6] = v1[1].z; a1[7] = v1[1].w;
#pragma unroll
        for (int k = 0; k < 8; k++) {
            float2 ph = cmulf(T0lo[((tid & 7) << 3) | k], hiC);
            ull sp = pk(a0[k], a1[k]);
            rp[k] = mul2(sp, pk(ph.x, ph.x));
            ip[k] = mul2(sp, pk(ph.y, ph.y));
        }
    }

    // named-barrier group ids
    const int gBC = 1 + ((tid >> 6) & 7);   // 2-warp groups (tid bits 6-8)
    const int gCD = 9 + ((tid >> 5) & 1);   // 8-warp groups (tid bit 5)

    // thread constants for the boundary scatter-write
    int T9 = tid; T9 ^= T9 >> 1; T9 ^= T9 >> 2; T9 ^= T9 >> 4; T9 ^= T9 >> 8;
    T9 &= 511;                              // suffix-XOR of tid (9 bits)
    const int pt6 = __popc(tid >> 6) & 1;   // parity of tid bits 6-8

    for (int l = 0; l < NL; l++) {
        const int bg = l * NW;

        // group A: bits 0-2 -> wires 11,10,9
        apply_group3(rp, ip, Ucs, bg, 11);

        // remap A -> B (intra-8-thread). No WAR barrier needed: slots
        // tid*9+k were last read by this thread (boundary read / fresh).
        {
            ulonglong2* wp = buf + tid * 9;
#pragma unroll
            for (int k = 0; k < 8; k++)
                wp[k] = make_ulonglong2(rp[k], ip[k]);  // pidx((tid<<3)|k)
        }
        __syncwarp();
#pragma unroll
        for (int k = 0; k < 8; k++) {
            int i = ((tid >> 3) << 6) | (k << 3) | (tid & 7);
            ulonglong2 v = buf[pidx(i)];
            rp[k] = v.x; ip[k] = v.y;
        }

        // group B: bits 3-5 -> wires 8,7,6
        apply_group3(rp, ip, Ucs, bg, 8);

        // remap B -> C. Write slots == A->B read slots (ownership).
#pragma unroll
        for (int k = 0; k < 8; k++) {
            int i = ((tid >> 3) << 6) | (k << 3) | (tid & 7);
            buf[pidx(i)] = make_ulonglong2(rp[k], ip[k]);
        }
        nbar(gBC, 64);
#pragma unroll
        for (int k = 0; k < 8; k++) {
            int i = ((tid >> 6) << 9) | (k << 6) | (tid & 63);
            ulonglong2 v = buf[pidx(i)];
            rp[k] = v.x; ip[k] = v.y;
        }

        // group C: bits 6-8 -> wires 5,4,3
        apply_group3(rp, ip, Ucs, bg, 5);

        // remap C -> D. Write slots == B->C read slots (ownership).
#pragma unroll
        for (int k = 0; k < 8; k++) {
            int i = ((tid >> 6) << 9) | (k << 6) | (tid & 63);
            buf[pidx(i)] = make_ulonglong2(rp[k], ip[k]);
        }
        nbar(gCD, 256);
#pragma unroll
        for (int k = 0; k < 8; k++) {
            int i = (k << 9) | tid;
            ulonglong2 v = buf[pidx(i)];
            rp[k] = v.x; ip[k] = v.y;
        }

        // group D: bits 9-11 -> wires 2,1,0
        apply_group3(rp, ip, Ucs, bg, 2);

        // boundary: CNOT perm + merged diagonal via WRITE-SCATTER.
        // Thread holds psi[i], i=(k<<9)|tid; dst y = sxor(i);
        // stores e^{i[phi1^{l+1}(y)+phi2^l(i)]} psi[i] at slot pidx(y).
        // Write pattern conflict-free; read is linear (= next A-write slots).
        if (l < NL - 1) {
            ull nr[8], ni[8];
            int ys[8];
            float2 lo0 = TLo[l][tid & 63];
            float2 lo1 = TLo[l][(tid & 63) | 64];
#pragma unroll
            for (int k = 0; k < 8; k++) {
                const int sx3 = k ^ (k >> 1) ^ (k >> 2);   // dst high bits
                const int pkk = sx3 & 1;                   // parity(k)
                ys[k] = (sx3 << 9) | (T9 ^ (pkk ? 511 : 0));
                float2 hi = THi[l][(k << 3) | (tid >> 6)];
                float2 ph = cmulf(hi, (pkk ^ pt6) ? lo1 : lo0);
                ull C = pk(ph.x, ph.x), S = pk(ph.y, ph.y), Sn = pk(-ph.y, -ph.y);
                nr[k] = fma2(Sn, ip[k], mul2(C, rp[k]));
                ni[k] = fma2(S, rp[k], mul2(C, ip[k]));
            }
            __syncthreads();   // WAR: scatter-write vs all C->D reads
#pragma unroll
            for (int k = 0; k < 8; k++)
                buf[pidx(ys[k])] = make_ulonglong2(nr[k], ni[k]);
            __syncthreads();   // RAW: linear reads see scattered writes
            {
                const ulonglong2* rpn = buf + tid * 9;
#pragma unroll
                for (int k = 0; k < 8; k++) {
                    ulonglong2 v = rpn[k];   // pidx((tid<<3)|k)
                    rp[k] = v.x; ip[k] = v.y;
                }
            }
        }
    }

    // ---- measurement (mapping D): final D2 dropped; last CNOT perm folded
    // into weights. x = (k<<9)|tid -> weight c(suffixXOR(x))
    int m9 = T9;   // suffix-XOR of tid (9 bits), computed above
    float c_low = 0.f;
#pragma unroll
    for (int w = 3; w < 12; w++) {
        c_low += ((m9 >> (11 - w)) & 1) ? -hw[w] : hw[w];
    }
    ull acc2 = 0ULL;
#pragma unroll
    for (int k = 0; k < 8; k++) {
        int g = k;
        g ^= g >> 1; g ^= g >> 2;  // 3-bit suffix-XOR
        float c_high = 0.f;
#pragma unroll
        for (int w = 0; w < 3; w++) {
            c_high += ((g >> (2 - w)) & 1) ? -hw[w] : hw[w];
        }
        float c = c_high + ((g & 1) ? -c_low : c_low);
        ull pr2 = fma2(rp[k], rp[k], mul2(ip[k], ip[k]));  // |psi|^2 both lanes
        acc2 = fma2(pr2, pk(c, c), acc2);
    }
#pragma unroll
    for (int o = 16; o > 0; o >>= 1) {
        float lo, hi;
        unpk(acc2, lo, hi);
        lo += __shfl_xor_sync(0xffffffffu, lo, o);
        hi += __shfl_xor_sync(0xffffffffu, hi, o);
        acc2 = pk(lo, hi);
    }
    if ((tid & 31) == 0) warpsum[tid >> 5] = acc2;
    __syncthreads();
    if (tid == 0) {
        float slo = 0.f, shi = 0.f;
#pragma unroll
        for (int i = 0; i < NT / 32; i++) {
            float lo, hi;
            unpk(warpsum[i], lo, hi);
            slo += lo; shi += hi;
        }
        float bias = head_b[0];
        out[r0] = slo + bias;
        if (has2) out[r1] = shi + bias;
    }
}

extern "C" void kernel_launch(void* const* d_in, const int* in_sizes, int n_in,
                              void* d_out, int out_size)
{
    const float* state   = (const float*)d_in[0];  // (512, 4096)
    const float* weights = (const float*)d_in[1];  // (3, 12, 3)
    const float* head_w  = (const float*)d_in[2];  // (1, 12)
    const float* head_b  = (const float*)d_in[3];  // (1,)
    float* out = (float*)d_out;                    // (512,)
    cudaFuncSetAttribute(qsim_kernel, cudaFuncAttributeMaxDynamicSharedMemorySize, DYN_SMEM);
    qsim_kernel<<<GRID, NT, DYN_SMEM>>>(state, weights, head_w, head_b, out);
}